// round 6
// baseline (speedup 1.0000x reference)
#include <cuda_runtime.h>
#include <math.h>

#define B 128
#define T 2048
#define D 64
#define H 128
#define O 32
#define NTH 512   // 16 warps: A = w0-7 (rec0), C = w8-15 (rec1); bursts use all

__device__ float g_s0[(size_t)B * T * H];   // xp0 scratch

// ---------------------------------------------------------------------------
// helpers
// ---------------------------------------------------------------------------
__device__ __forceinline__ unsigned long long ffma2(unsigned long long a,
                                                    unsigned long long b,
                                                    unsigned long long c) {
    unsigned long long d;
    asm("fma.rn.f32x2 %0, %1, %2, %3;" : "=l"(d) : "l"(a), "l"(b), "l"(c));
    return d;
}
__device__ __forceinline__ unsigned long long addf2(unsigned long long a,
                                                    unsigned long long b) {
    unsigned long long d;
    asm("add.rn.f32x2 %0, %1, %2;" : "=l"(d) : "l"(a), "l"(b));
    return d;
}
__device__ __forceinline__ float f2lo(unsigned long long v) {
    return __uint_as_float((unsigned)(v & 0xffffffffull));
}
__device__ __forceinline__ float f2hi(unsigned long long v) {
    return __uint_as_float((unsigned)(v >> 32));
}
__device__ __forceinline__ float tanh_fast(float x) {
    float y;
    asm("tanh.approx.f32 %0, %1;" : "=f"(y) : "f"(x));
    return y;
}

// ---------------------------------------------------------------------------
// Input projection (layer 0): xp0[b,t,j] = x[b,t,:]·W_ih0[j,:] + b_ih0 + b_hh0
// ---------------------------------------------------------------------------
template <int K>
__global__ __launch_bounds__(128) void proj_kernel(
    const float* __restrict__ in, float* __restrict__ out,
    const float* __restrict__ W, const float* __restrict__ b1,
    const float* __restrict__ b2, const int* __restrict__ lengths)
{
    constexpr int CT = 16;
    const int b  = blockIdx.y;
    const int t0 = blockIdx.x * CT;
    const int len = lengths[b];
    if (t0 >= len) return;

    const int j = threadIdx.x;
    __shared__ __align__(16) float xs[CT][K];

    unsigned long long wq[K / 2];
    {
        const ulonglong2* Wp = (const ulonglong2*)(W + (size_t)j * K);
#pragma unroll
        for (int i = 0; i < K / 4; ++i) {
            ulonglong2 v = Wp[i];
            wq[2 * i] = v.x; wq[2 * i + 1] = v.y;
        }
    }
    const float bias = b1[j] + b2[j];

    const int nt = min(CT, len - t0);
    const float* inp = in + ((size_t)b * T + t0) * K;
    for (int idx = j; idx < nt * K / 4; idx += 128)
        ((float4*)xs)[idx] = ((const float4*)inp)[idx];
    __syncthreads();

    for (int tt = 0; tt < nt; ++tt) {
        unsigned long long a0 = 0ull, a1 = 0ull;
        const ulonglong2* xr = (const ulonglong2*)&xs[tt][0];
#pragma unroll
        for (int i = 0; i < K / 4; ++i) {
            ulonglong2 hv = xr[i];
            a0 = ffma2(wq[2 * i], hv.x, a0);
            a1 = ffma2(wq[2 * i + 1], hv.y, a1);
        }
        unsigned long long a = addf2(a0, a1);
        out[((size_t)b * T + t0 + tt) * H + j] = bias + f2lo(a) + f2hi(a);
    }
}

// ---------------------------------------------------------------------------
// FC tile of 8 steps starting at tb: out[b,t,o] = Wfc[o,:]·h2[t,:] + bfc[o].
// 256 dots (8t x 32o), 2 lanes per dot (k-half). Wfc via LDG (L1-resident).
// Stores guarded by t < len; compute unconditional (stale smem reads are safe).
// ---------------------------------------------------------------------------
__device__ __forceinline__ void fc_tile8(
    const float* __restrict__ h2r, const float* __restrict__ bfcs,
    const float* __restrict__ Wfc, float* __restrict__ obase,
    int tb, int len, int tid)
{
    const int d  = tid >> 1;          // 0..255
    const int hh = tid & 1;           // k-half
    const int t  = tb + (d >> 5);
    const int o  = d & 31;
    const float* wg = Wfc + (size_t)o * H + hh * 64;
    const float* hr = h2r + (t & 31) * H + hh * 64;
    unsigned long long a0 = 0ull, a1 = 0ull;
#pragma unroll
    for (int c = 0; c < 16; ++c) {
        ulonglong2 wv = *(const ulonglong2*)(wg + 4 * c);
        ulonglong2 hv = *(const ulonglong2*)(hr + 4 * c);
        a0 = ffma2(wv.x, hv.x, a0);
        a1 = ffma2(wv.y, hv.y, a1);
    }
    unsigned long long a = addf2(a0, a1);
    float s = f2lo(a) + f2hi(a);
    s += __shfl_xor_sync(0xffffffffu, s, 1);
    if (hh == 0 && t < len) obase[(size_t)t * O + o] = s + bfcs[o];
}

// ---------------------------------------------------------------------------
// Fused kernel: one CTA (16 warps) per batch row.
//  every iter i:  A (w0-7):  h1[i]  = tanh(xp0[i] + Whh0·h1[i-1])      i<len
//                 C (w8-15): h2[s]  = tanh(xp1[s] + Whh1·h2[s-1]), s=i-9
//  every 8th iter (all 512 threads, bursts):
//     xs:  stream xp0 tile [i+8, i+15] into smem ring
//     P:   xp1 tile [i-8, i-1] = Wih1·h1 + bias   (Wih1 via LDG, L1-resident)
//     FC:  out tile [i-24, i-17] from h2 history  (Wfc via LDG)
//  One __syncthreads per iteration; ring depths make all phases disjoint.
// ---------------------------------------------------------------------------
__global__ __launch_bounds__(NTH, 1) void fused_kernel(
    const float* __restrict__ xp0,
    const float* __restrict__ Whh0,
    const float* __restrict__ Wih1,
    const float* __restrict__ Whh1,
    const float* __restrict__ b_ih1,
    const float* __restrict__ b_hh1,
    const float* __restrict__ Wfc,
    const float* __restrict__ bfc,
    const int* __restrict__ lengths,
    float* __restrict__ out)
{
    __shared__ __align__(16) float h1r[16 * H];   // h1 history ring
    __shared__ __align__(16) float h2r[32 * H];   // h2 history ring
    __shared__ __align__(16) float xp1r[16 * H];  // xp1 ring (bias included)
    __shared__ __align__(16) float xsr[16 * H];   // xp0 ring
    __shared__ __align__(16) float bi1[H];
    __shared__ __align__(16) float bfcs[O];

    const int b    = blockIdx.x;
    const int tid  = threadIdx.x;
    const int lane = tid & 31;
    const int w    = tid >> 5;
    const int len  = lengths[b];
    const bool isA = (w < 8);

    if (tid < H) {
        bi1[tid] = b_ih1[tid] + b_hh1[tid];
        h1r[15 * H + tid] = 0.0f;   // h1[-1]
        h2r[31 * H + tid] = 0.0f;   // h2[-1]
    }
    if (tid < O) bfcs[tid] = bfc[tid];

    // recurrence weights in registers: 64 floats/thread (2-lane k-split)
    const int j    = (isA ? w : (w - 8)) * 16 + (lane >> 1);
    const int sel4 = (lane & 1) * 4;
    unsigned long long wq[32];
    {
        const float* wr = (isA ? Whh0 : Whh1) + (size_t)j * H + sel4;
#pragma unroll
        for (int ic = 0; ic < 16; ++ic) {
            ulonglong2 v = *(const ulonglong2*)(wr + 8 * ic);
            wq[2 * ic] = v.x; wq[2 * ic + 1] = v.y;
        }
    }

    // preload xp0 tiles t = 0..15 (one float4 per thread)
    const float* xbase = xp0 + (size_t)b * T * H;
    {
        int t = tid >> 5, c = lane;
        *(float4*)&xsr[t * H + c * 4] =
            *(const float4*)(xbase + (size_t)t * H + c * 4);
    }
    __syncthreads();

    float* obase = out + (size_t)b * T * O;
    const int i_end = len + 8;

    for (int i = 0; i <= i_end; ++i) {
        if (((i & 7) == 0) && i >= 8) {
            // ---- xs burst: load xp0 tile [i+8, i+15] ----
            if (tid < 256) {
                int t = i + 8 + (tid >> 5);
                if (t < T) {
                    int c = tid & 31;
                    *(float4*)&xsr[(t & 15) * H + c * 4] =
                        *(const float4*)(xbase + (size_t)t * H + c * 4);
                }
            }
            // ---- P burst: xp1 tile tb = i-8 (128 engines x 4-lane k-split) ----
            {
                const int e  = tid >> 2;      // output row j = e
                const int q  = tid & 3;       // k-quarter
                const int tb = i - 8;
                const float* wgt = Wih1 + (size_t)e * H + q * 32;
                const float* hb[8];
#pragma unroll
                for (int t = 0; t < 8; ++t)
                    hb[t] = &h1r[((tb + t) & 15) * H + q * 32];
                unsigned long long acc[8];
#pragma unroll
                for (int t = 0; t < 8; ++t) acc[t] = 0ull;
#pragma unroll
                for (int c = 0; c < 8; ++c) {
                    ulonglong2 wv = *(const ulonglong2*)(wgt + 4 * c);
#pragma unroll
                    for (int t = 0; t < 8; ++t) {
                        ulonglong2 hv = *(const ulonglong2*)(hb[t] + 4 * c);
                        acc[t] = ffma2(wv.x, hv.x, acc[t]);
                        acc[t] = ffma2(wv.y, hv.y, acc[t]);
                    }
                }
#pragma unroll
                for (int t = 0; t < 8; ++t) {
                    float s = f2lo(acc[t]) + f2hi(acc[t]);
                    s += __shfl_xor_sync(0xffffffffu, s, 1);
                    s += __shfl_xor_sync(0xffffffffu, s, 2);
                    if (q == 0 && (tb + t) < len)
                        xp1r[((tb + t) & 15) * H + e] = s + bi1[e];
                }
            }
            // ---- FC burst: out tile [i-24, i-17] ----
            if (i >= 24)
                fc_tile8(h2r, bfcs, Wfc, obase, i - 24, len, tid);
        }

        // ---- recurrence phase ----
        if (isA) {
            if (i < len) {
                const float* src = &h1r[((i + 15) & 15) * H + sel4];
                unsigned long long a0 = 0ull, a1 = 0ull;
#pragma unroll
                for (int ic = 0; ic < 16; ++ic) {
                    ulonglong2 hv = *(const ulonglong2*)(src + 8 * ic);
                    a0 = ffma2(wq[2 * ic],     hv.x, a0);
                    a1 = ffma2(wq[2 * ic + 1], hv.y, a1);
                }
                unsigned long long a = addf2(a0, a1);
                float s = f2lo(a) + f2hi(a);
                s += __shfl_xor_sync(0xffffffffu, s, 1);
                float hn = tanh_fast(s + xsr[(i & 15) * H + j]);
                if ((lane & 1) == 0) h1r[(i & 15) * H + j] = hn;
            }
        } else {
            const int ss = i - 9;
            if (ss >= 0 && ss < len) {
                const float* src = &h2r[((ss + 31) & 31) * H + sel4];
                unsigned long long a0 = 0ull, a1 = 0ull;
#pragma unroll
                for (int ic = 0; ic < 16; ++ic) {
                    ulonglong2 hv = *(const ulonglong2*)(src + 8 * ic);
                    a0 = ffma2(wq[2 * ic],     hv.x, a0);
                    a1 = ffma2(wq[2 * ic + 1], hv.y, a1);
                }
                unsigned long long a = addf2(a0, a1);
                float s = f2lo(a) + f2hi(a);
                s += __shfl_xor_sync(0xffffffffu, s, 1);
                float hn = tanh_fast(s + xp1r[(ss & 15) * H + j]);
                if ((lane & 1) == 0) h2r[(ss & 31) * H + j] = hn;
            }
        }
        __syncthreads();
    }

    // ---- FC cleanup: steps not covered by in-loop bursts ----
    {
        const int last = ((len + 8) >> 3) << 3;   // last in-loop burst iter
        int tb = last - 16; if (tb < 0) tb = 0;
        for (; tb < len; tb += 8)
            fc_tile8(h2r, bfcs, Wfc, obase, tb, len, tid);
    }

    // ---- padded rows: out[b, t>=len, :] = b_fc ----
    {
        float* op = obase + (size_t)len * O;
        const int n4 = (T - len) * (O / 4);
        const float4* bv = (const float4*)bfcs;
        for (int idx = tid; idx < n4; idx += NTH)
            ((float4*)op)[idx] = bv[idx & 7];
    }
}

// ---------------------------------------------------------------------------
extern "C" void kernel_launch(void* const* d_in, const int* in_sizes, int n_in,
                              void* d_out, int out_size)
{
    const float* x      = (const float*)d_in[0];
    const int*   lens   = (const int*)  d_in[1];
    const float* W_ih0  = (const float*)d_in[2];
    const float* W_hh0  = (const float*)d_in[3];
    const float* b_ih0  = (const float*)d_in[4];
    const float* b_hh0  = (const float*)d_in[5];
    const float* W_ih1  = (const float*)d_in[6];
    const float* W_hh1  = (const float*)d_in[7];
    const float* b_ih1  = (const float*)d_in[8];
    const float* b_hh1  = (const float*)d_in[9];
    const float* W_fc   = (const float*)d_in[10];
    const float* b_fc   = (const float*)d_in[11];
    float* out = (float*)d_out;

    float* s0;
    cudaGetSymbolAddress((void**)&s0, g_s0);

    dim3 pgrid(T / 16, B);
    proj_kernel<D><<<pgrid, 128>>>(x, s0, W_ih0, b_ih0, b_hh0, lens);
    fused_kernel<<<B, NTH>>>(s0, W_hh0, W_ih1, W_hh1,
                             b_ih1, b_hh1, W_fc, b_fc, lens, out);
}